// round 3
// baseline (speedup 1.0000x reference)
#include <cuda_runtime.h>
#include <cstdint>

#define NSEQ 128
#define TB   4096
#define FIN  208
#define HGRU 131
#define HP   132      // padded hidden (even, 16B-aligned rows)
#define G3   393      // 3*H
#define G3P  416      // padded 3*H (13 warps)
#define DMLP 255
#define DOUT 17

#define NREGP 56      // GRU weight pairs in registers (112 floats)
#define NTAIL 10      // GRU weight pairs in smem (20 floats incl 1 pad)

typedef unsigned long long ull;

// ---- scratch (__device__ globals; zero-initialized at module load) ----
__device__ float g_wpad[G3 * HP];        // W_hh padded [393][132]
__device__ float g_gi[NSEQ * G3];        // input preactivations, lane 4095
__device__ float g_x[NSEQ * HP];         // GRU outputs, pitch 132, col131==0
__device__ float g_wiht[FIN * G3P];      // W_ih^T padded [208][416]
__device__ float g_bihp[G3P];            // b_ih padded
__device__ float g_wmt[5][256 * 256];    // W1..W5 transposed+padded [k][c]
__device__ float g_bmp[5][256];          // b1..b5 padded
__device__ float g_w6t[256 * 32];        // W6^T padded [k][c]
__device__ float g_b6p[32];

// ---- prep: pad + transpose all weights (runs every call, ~3-4us) ----
__global__ void prep_kernel(const float* __restrict__ Whh,
                            const float* __restrict__ Wih,
                            const float* __restrict__ bih,
                            const float* __restrict__ W1, const float* __restrict__ b1,
                            const float* __restrict__ W2, const float* __restrict__ b2,
                            const float* __restrict__ W3, const float* __restrict__ b3,
                            const float* __restrict__ W4, const float* __restrict__ b4,
                            const float* __restrict__ W5, const float* __restrict__ b5,
                            const float* __restrict__ W6, const float* __restrict__ b6)
{
    int idx = blockIdx.x * blockDim.x + threadIdx.x;

    if (idx < G3 * HP) {                               // W_hh pad
        int j = idx / HP, k = idx - j * HP;
        g_wpad[idx] = (k < HGRU) ? Whh[j * HGRU + k] : 0.f;
        return;
    }
    idx -= G3 * HP;
    if (idx < FIN * G3P) {                             // W_ih transpose
        int k = idx / G3P, j = idx - k * G3P;
        g_wiht[idx] = (j < G3) ? Wih[j * FIN + k] : 0.f;
        return;
    }
    idx -= FIN * G3P;
    if (idx < G3P) {                                   // b_ih pad
        g_bihp[idx] = (idx < G3) ? bih[idx] : 0.f;
        return;
    }
    idx -= G3P;
    if (idx < 5 * 256 * 256) {                         // W1..W5 transpose
        int l = idx >> 16, r = idx & 65535;
        int k = r >> 8, c = r & 255;
        const float* W = (l == 0) ? W1 : (l == 1) ? W2 : (l == 2) ? W3
                        : (l == 3) ? W4 : W5;
        int din = (l == 0) ? HGRU : DMLP;
        g_wmt[l][r] = (c < DMLP && k < din) ? W[c * din + k] : 0.f;
        return;
    }
    idx -= 5 * 256 * 256;
    if (idx < 5 * 256) {                               // b1..b5 pad
        int l = idx >> 8, c = idx & 255;
        const float* B = (l == 0) ? b1 : (l == 1) ? b2 : (l == 2) ? b3
                        : (l == 3) ? b4 : b5;
        g_bmp[l][c] = (c < DMLP) ? B[c] : 0.f;
        return;
    }
    idx -= 5 * 256;
    if (idx < 256 * 32) {                              // W6 transpose
        int k = idx >> 5, c = idx & 31;
        g_w6t[idx] = (c < DOUT && k < DMLP) ? W6[c * DMLP + k] : 0.f;
        return;
    }
    idx -= 256 * 32;
    if (idx < 32) g_b6p[idx] = (idx < DOUT) ? b6[idx] : 0.f;
}

// ---- gi projection: gi[n][j] = hist[n,4095,:] . W_ih[j,:] + b_ih[j] ----
// CTA = 2 rows x 416 cols; coalesced transposed-W LDG; x broadcast from SMEM.
__global__ __launch_bounds__(G3P) void gi_kernel(const float* __restrict__ hist)
{
    __shared__ float2 xs[FIN];
    const int j = threadIdx.x;
    const int r0 = blockIdx.x * 2;

    const float* h0 = hist + ((size_t)r0 * TB + (TB - 1)) * FIN;
    const float* h1 = hist + ((size_t)(r0 + 1) * TB + (TB - 1)) * FIN;
    for (int k = j; k < FIN; k += G3P) xs[k] = make_float2(h0[k], h1[k]);
    __syncthreads();

    float bv = g_bihp[j];
    float a0 = bv, a1 = bv;
#pragma unroll 4
    for (int k = 0; k < FIN; k++) {
        float w = g_wiht[k * G3P + j];
        float2 x = xs[k];
        a0 = fmaf(x.x, w, a0);
        a1 = fmaf(x.y, w, a1);
    }
    if (j < G3) {
        g_gi[r0 * G3 + j]       = a0;
        g_gi[(r0 + 1) * G3 + j] = a1;
    }
}

// ---- fused 6-layer MLP: one kernel, 2 rows/CTA, SMEM ping-pong ----
__global__ __launch_bounds__(256) void mlp_kernel(float* __restrict__ out)
{
    __shared__ float2 buf[2][256];
    const int c = threadIdx.x;
    const int r0 = blockIdx.x * 2;

    float2 v = make_float2(0.f, 0.f);
    if (c < HGRU) v = make_float2(g_x[r0 * HP + c], g_x[(r0 + 1) * HP + c]);
    buf[0][c] = v;
    __syncthreads();

    int cur = 0;
#pragma unroll
    for (int l = 0; l < 5; l++) {
        const float* wt = g_wmt[l];
        const int kin = (l == 0) ? HP : 256;
        float bv = g_bmp[l][c];
        float a0 = bv, a1 = bv;
#pragma unroll 4
        for (int k = 0; k < kin; k++) {
            float w = wt[k * 256 + c];
            float2 x = buf[cur][k];
            a0 = fmaf(x.x, w, a0);
            a1 = fmaf(x.y, w, a1);
        }
        buf[cur ^ 1][c] = make_float2(fmaxf(a0, 0.f), fmaxf(a1, 0.f));
        __syncthreads();
        cur ^= 1;
    }

    if (c < 32) {
        float bv = g_b6p[c];
        float a0 = bv, a1 = bv;
#pragma unroll 4
        for (int k = 0; k < DMLP; k++) {
            float w = g_w6t[k * 32 + c];
            float2 x = buf[cur][k];
            a0 = fmaf(x.x, w, a0);
            a1 = fmaf(x.y, w, a1);
        }
        if (c < DOUT) {
            out[r0 * DOUT + c]       = a0;
            out[(r0 + 1) * DOUT + c] = a1;
        }
    }
}

// ---- GRU recurrence (unchanged from R2): 112 reg + 20 smem weight floats --
__device__ __forceinline__ float fast_sigmoid(float x) {
    return 1.f / (1.f + __expf(-x));
}
__device__ __forceinline__ float fast_tanh(float x) {
    float e = __expf(-2.f * x);
    return (1.f - e) / (1.f + e);
}

__global__ __launch_bounds__(416, 1) void gru_kernel(const float* __restrict__ b_hh)
{
    __shared__ __align__(16) float h_sh[HP];
    __shared__ float gh_sh[G3];
    __shared__ float gi_sh[G3];
    __shared__ ull tail_w[NTAIL][416];

    const int j = threadIdx.x;

    ull w2[NREGP];
    float bj = 0.f;
    if (j < G3) {
        const ull* wr = reinterpret_cast<const ull*>(g_wpad + j * HP);
#pragma unroll
        for (int i = 0; i < NREGP; i++) w2[i] = wr[i];
#pragma unroll
        for (int t = 0; t < NTAIL; t++) tail_w[t][j] = wr[NREGP + t];
        bj = b_hh[j];
    }
    if (j < HP) h_sh[j] = 0.f;

    uint32_t h_addr;
    asm("{ .reg .u64 t; cvta.to.shared.u64 t, %1; cvt.u32.u64 %0, t; }"
        : "=r"(h_addr) : "l"(h_sh));

    float gi_v = (j < G3) ? g_gi[j] : 0.f;
    __syncthreads();

    for (int n = 0; n < NSEQ; n++) {
        float gi_cur = gi_v;
        if (j < G3 && n + 1 < NSEQ) gi_v = __ldg(g_gi + (n + 1) * G3 + j);

        if (j < G3) {
            ull acc0, acc1 = 0ULL;
            asm("mov.b64 %0, {%1, %2};" : "=l"(acc0) : "f"(bj), "f"(0.f));
#pragma unroll
            for (int i = 0; i < NREGP / 2; i++) {
                ull h0, h1;
                asm volatile("ld.shared.v2.u64 {%0, %1}, [%2];"
                             : "=l"(h0), "=l"(h1) : "r"(h_addr + i * 16));
                asm("fma.rn.f32x2 %0, %1, %2, %0;" : "+l"(acc0)
                    : "l"(h0), "l"(w2[2 * i]));
                asm("fma.rn.f32x2 %0, %1, %2, %0;" : "+l"(acc1)
                    : "l"(h1), "l"(w2[2 * i + 1]));
            }
#pragma unroll
            for (int t = 0; t < NTAIL / 2; t++) {
                ull h0, h1;
                asm volatile("ld.shared.v2.u64 {%0, %1}, [%2];"
                             : "=l"(h0), "=l"(h1)
                             : "r"(h_addr + (NREGP + 2 * t) * 8));
                ull tw0 = tail_w[2 * t][j];
                ull tw1 = tail_w[2 * t + 1][j];
                asm("fma.rn.f32x2 %0, %1, %2, %0;" : "+l"(acc0)
                    : "l"(h0), "l"(tw0));
                asm("fma.rn.f32x2 %0, %1, %2, %0;" : "+l"(acc1)
                    : "l"(h1), "l"(tw1));
            }
            float a0, a1, a2, a3;
            asm("mov.b64 {%0, %1}, %2;" : "=f"(a0), "=f"(a1) : "l"(acc0));
            asm("mov.b64 {%0, %1}, %2;" : "=f"(a2), "=f"(a3) : "l"(acc1));
            gh_sh[j] = (a0 + a2) + (a1 + a3);
            gi_sh[j] = gi_cur;
        }
        __syncthreads();

        if (j < HGRU) {
            float ir = gi_sh[j], iz = gi_sh[j + HGRU], in_ = gi_sh[j + 2 * HGRU];
            float hr = gh_sh[j], hz = gh_sh[j + HGRU], hn = gh_sh[j + 2 * HGRU];
            float r  = fast_sigmoid(ir + hr);
            float z  = fast_sigmoid(iz + hz);
            float nn = fast_tanh(in_ + r * hn);
            float hp = h_sh[j];
            float hnew = nn + z * (hp - nn);
            h_sh[j] = hnew;
            g_x[n * HP + j] = hnew;
        }
        __syncthreads();
    }
}

// ---- empty dummies: shift GRU to profiled launch slot #6 (-s 5 -c 1) ----
__global__ void dummy_kernel() {}

extern "C" void kernel_launch(void* const* d_in, const int* in_sizes, int n_in,
                              void* d_out, int out_size)
{
    const float* history = (const float*)d_in[0];
    const float* W_ih = (const float*)d_in[1];
    const float* W_hh = (const float*)d_in[2];
    const float* b_ih = (const float*)d_in[3];
    const float* b_hh = (const float*)d_in[4];
    const float* W1 = (const float*)d_in[5];  const float* b1 = (const float*)d_in[6];
    const float* W2 = (const float*)d_in[7];  const float* b2 = (const float*)d_in[8];
    const float* W3 = (const float*)d_in[9];  const float* b3 = (const float*)d_in[10];
    const float* W4 = (const float*)d_in[11]; const float* b4 = (const float*)d_in[12];
    const float* W5 = (const float*)d_in[13]; const float* b5 = (const float*)d_in[14];
    const float* W6 = (const float*)d_in[15]; const float* b6 = (const float*)d_in[16];
    float* out = (float*)d_out;

    const int prep_total = G3 * HP + FIN * G3P + G3P
                         + 5 * 256 * 256 + 5 * 256 + 256 * 32 + 32;

    prep_kernel<<<(prep_total + 511) / 512, 512>>>(                 // launch 1
        W_hh, W_ih, b_ih, W1, b1, W2, b2, W3, b3, W4, b4, W5, b5, W6, b6);

    gi_kernel<<<NSEQ / 2, G3P>>>(history);                          // launch 2

    dummy_kernel<<<1, 32>>>();                                      // launch 3
    dummy_kernel<<<1, 32>>>();                                      // launch 4
    dummy_kernel<<<1, 32>>>();                                      // launch 5

    gru_kernel<<<1, 416>>>(b_hh);                                   // launch 6 (profiled)

    mlp_kernel<<<NSEQ / 2, 256>>>(out);                             // launch 7
}

// round 4
// speedup vs baseline: 1.3278x; 1.3278x over previous
#include <cuda_runtime.h>
#include <cstdint>

#define NSEQ 128
#define TB   4096
#define FIN  208
#define HGRU 131
#define HP   132      // padded hidden (even, 16B-aligned rows)
#define G3   393      // 3*H
#define G3P  416      // padded 3*H (13 warps)
#define DMLP 255
#define DOUT 17

#define NREGP 48      // GRU weight pairs in registers (96 floats)
#define NTAIL 18      // GRU weight pairs in smem (36 floats incl 1 pad)

typedef unsigned long long ull;

// ---- scratch (__device__ globals) ----
__device__ float g_wpad[G3 * HP];        // W_hh padded [393][132]
__device__ float g_gi[NSEQ * G3];        // input preactivations, lane 4095
__device__ float g_x[NSEQ * HP];         // GRU outputs, pitch 132, col131==0
__device__ float g_wiht[FIN * G3P];      // W_ih^T padded [208][416]
__device__ float g_bihp[G3P];            // b_ih padded
__device__ float g_wmt[5][256 * 256];    // W1..W5 transposed+padded [k][c]
__device__ float g_bmp[5][256];          // b1..b5 padded
__device__ float g_w6t[256 * 32];        // W6^T padded [k][c]
__device__ float g_b6p[32];

// ---- prep: pad + transpose all weights ----
__global__ void prep_kernel(const float* __restrict__ Whh,
                            const float* __restrict__ Wih,
                            const float* __restrict__ bih,
                            const float* __restrict__ W1, const float* __restrict__ b1,
                            const float* __restrict__ W2, const float* __restrict__ b2,
                            const float* __restrict__ W3, const float* __restrict__ b3,
                            const float* __restrict__ W4, const float* __restrict__ b4,
                            const float* __restrict__ W5, const float* __restrict__ b5,
                            const float* __restrict__ W6, const float* __restrict__ b6)
{
    int idx = blockIdx.x * blockDim.x + threadIdx.x;

    if (idx < G3 * HP) {
        int j = idx / HP, k = idx - j * HP;
        g_wpad[idx] = (k < HGRU) ? Whh[j * HGRU + k] : 0.f;
        return;
    }
    idx -= G3 * HP;
    if (idx < FIN * G3P) {
        int k = idx / G3P, j = idx - k * G3P;
        g_wiht[idx] = (j < G3) ? Wih[j * FIN + k] : 0.f;
        return;
    }
    idx -= FIN * G3P;
    if (idx < G3P) {
        g_bihp[idx] = (idx < G3) ? bih[idx] : 0.f;
        return;
    }
    idx -= G3P;
    if (idx < 5 * 256 * 256) {
        int l = idx >> 16, r = idx & 65535;
        int k = r >> 8, c = r & 255;
        const float* W = (l == 0) ? W1 : (l == 1) ? W2 : (l == 2) ? W3
                        : (l == 3) ? W4 : W5;
        int din = (l == 0) ? HGRU : DMLP;
        g_wmt[l][r] = (c < DMLP && k < din) ? W[c * din + k] : 0.f;
        return;
    }
    idx -= 5 * 256 * 256;
    if (idx < 5 * 256) {
        int l = idx >> 8, c = idx & 255;
        const float* B = (l == 0) ? b1 : (l == 1) ? b2 : (l == 2) ? b3
                        : (l == 3) ? b4 : b5;
        g_bmp[l][c] = (c < DMLP) ? B[c] : 0.f;
        return;
    }
    idx -= 5 * 256;
    if (idx < 256 * 32) {
        int k = idx >> 5, c = idx & 31;
        g_w6t[idx] = (c < DOUT && k < DMLP) ? W6[c * DMLP + k] : 0.f;
        return;
    }
    idx -= 256 * 32;
    if (idx < 32) g_b6p[idx] = (idx < DOUT) ? b6[idx] : 0.f;
}

// ---- gi projection ----
__global__ __launch_bounds__(G3P) void gi_kernel(const float* __restrict__ hist)
{
    __shared__ float2 xs[FIN];
    const int j = threadIdx.x;
    const int r0 = blockIdx.x * 2;

    const float* h0 = hist + ((size_t)r0 * TB + (TB - 1)) * FIN;
    const float* h1 = hist + ((size_t)(r0 + 1) * TB + (TB - 1)) * FIN;
    for (int k = j; k < FIN; k += G3P) xs[k] = make_float2(h0[k], h1[k]);
    __syncthreads();

    float bv = g_bihp[j];
    float a0 = bv, a1 = bv;
#pragma unroll 16
    for (int k = 0; k < FIN; k++) {
        float w = g_wiht[k * G3P + j];
        float2 x = xs[k];
        a0 = fmaf(x.x, w, a0);
        a1 = fmaf(x.y, w, a1);
    }
    if (j < G3) {
        g_gi[r0 * G3 + j]       = a0;
        g_gi[(r0 + 1) * G3 + j] = a1;
    }
}

// ---- fused 6-layer MLP ----
__global__ __launch_bounds__(256) void mlp_kernel(float* __restrict__ out)
{
    __shared__ float2 buf[2][256];
    const int c = threadIdx.x;
    const int r0 = blockIdx.x * 2;

    float2 v = make_float2(0.f, 0.f);
    if (c < HGRU) v = make_float2(g_x[r0 * HP + c], g_x[(r0 + 1) * HP + c]);
    buf[0][c] = v;
    __syncthreads();

    int cur = 0;
#pragma unroll
    for (int l = 0; l < 5; l++) {
        const float* wt = g_wmt[l];
        const int kin = (l == 0) ? HP : 256;
        float bv = g_bmp[l][c];
        float a0 = bv, a1 = bv;
#pragma unroll 16
        for (int k = 0; k < kin; k++) {
            float w = wt[k * 256 + c];
            float2 x = buf[cur][k];
            a0 = fmaf(x.x, w, a0);
            a1 = fmaf(x.y, w, a1);
        }
        buf[cur ^ 1][c] = make_float2(fmaxf(a0, 0.f), fmaxf(a1, 0.f));
        __syncthreads();
        cur ^= 1;
    }

    if (c < 32) {
        float bv = g_b6p[c];
        float a0 = bv, a1 = bv;
#pragma unroll 16
        for (int k = 0; k < DMLP; k++) {
            float w = g_w6t[k * 32 + c];
            float2 x = buf[cur][k];
            a0 = fmaf(x.x, w, a0);
            a1 = fmaf(x.y, w, a1);
        }
        if (c < DOUT) {
            out[r0 * DOUT + c]       = a0;
            out[(r0 + 1) * DOUT + c] = a1;
        }
    }
}

// ---- GRU recurrence: compiler-scheduled smem loads + non-volatile f32x2 ----
__device__ __forceinline__ float fast_sigmoid(float x) {
    return 1.f / (1.f + __expf(-x));
}
__device__ __forceinline__ float fast_tanh(float x) {
    float e = __expf(-2.f * x);
    return (1.f - e) / (1.f + e);
}
__device__ __forceinline__ void fma2(ull& acc, ull h, ull w) {
    asm("fma.rn.f32x2 %0, %1, %2, %0;" : "+l"(acc) : "l"(h), "l"(w));
}

__global__ __launch_bounds__(416, 1) void gru_kernel(const float* __restrict__ b_hh)
{
    __shared__ __align__(16) float h_sh[HP];
    __shared__ float gh_sh[G3];
    __shared__ float gi_sh[G3];
    __shared__ ull tail_w[NTAIL][416];

    const int j = threadIdx.x;

    ull w2[NREGP];
    float bj = 0.f;
    if (j < G3) {
        const ull* wr = reinterpret_cast<const ull*>(g_wpad + j * HP);
#pragma unroll
        for (int i = 0; i < NREGP; i++) w2[i] = wr[i];
#pragma unroll
        for (int t = 0; t < NTAIL; t++) tail_w[t][j] = wr[NREGP + t];
        bj = b_hh[j];
    }
    if (j < HP) h_sh[j] = 0.f;

    float gi_v = (j < G3) ? g_gi[j] : 0.f;
    __syncthreads();

    const ulonglong2* hv2 = reinterpret_cast<const ulonglong2*>(h_sh);
    const ull* hv = reinterpret_cast<const ull*>(h_sh);

    for (int n = 0; n < NSEQ; n++) {
        float gi_cur = gi_v;
        if (j < G3 && n + 1 < NSEQ) gi_v = __ldg(g_gi + (n + 1) * G3 + j);

        if (j < G3) {
            ull acc0, acc1 = 0ULL;
            asm("mov.b64 %0, {%1, %2};" : "=l"(acc0) : "f"(bj), "f"(0.f));
            // register-resident part: pairs 0..47 (floats 0..95)
#pragma unroll
            for (int i = 0; i < NREGP / 2; i++) {
                ulonglong2 h = hv2[i];            // plain LDS.128 (broadcast)
                fma2(acc0, h.x, w2[2 * i]);
                fma2(acc1, h.y, w2[2 * i + 1]);
            }
            // smem tail: pairs 48..65 (floats 96..131, last is zero pad)
#pragma unroll
            for (int t = 0; t < NTAIL / 2; t++) {
                ulonglong2 h = hv2[NREGP / 2 + t];
                fma2(acc0, h.x, tail_w[2 * t][j]);
                fma2(acc1, h.y, tail_w[2 * t + 1][j]);
            }
            float a0, a1, a2, a3;
            asm("mov.b64 {%0, %1}, %2;" : "=f"(a0), "=f"(a1) : "l"(acc0));
            asm("mov.b64 {%0, %1}, %2;" : "=f"(a2), "=f"(a3) : "l"(acc1));
            gh_sh[j] = (a0 + a2) + (a1 + a3);
            gi_sh[j] = gi_cur;
        }
        __syncthreads();

        if (j < HGRU) {
            float ir = gi_sh[j], iz = gi_sh[j + HGRU], in_ = gi_sh[j + 2 * HGRU];
            float hr = gh_sh[j], hz = gh_sh[j + HGRU], hn = gh_sh[j + 2 * HGRU];
            float r  = fast_sigmoid(ir + hr);
            float z  = fast_sigmoid(iz + hz);
            float nn = fast_tanh(in_ + r * hn);
            float hp = h_sh[j];
            float hnew = nn + z * (hp - nn);
            h_sh[j] = hnew;
            g_x[n * HP + j] = hnew;
        }
        __syncthreads();
    }
    (void)hv;
}

// ---- dummy: shifts gru_kernel into profiled launch slot #4 ----
__global__ void dummy_kernel() {}

extern "C" void kernel_launch(void* const* d_in, const int* in_sizes, int n_in,
                              void* d_out, int out_size)
{
    const float* history = (const float*)d_in[0];
    const float* W_ih = (const float*)d_in[1];
    const float* W_hh = (const float*)d_in[2];
    const float* b_ih = (const float*)d_in[3];
    const float* b_hh = (const float*)d_in[4];
    const float* W1 = (const float*)d_in[5];  const float* b1 = (const float*)d_in[6];
    const float* W2 = (const float*)d_in[7];  const float* b2 = (const float*)d_in[8];
    const float* W3 = (const float*)d_in[9];  const float* b3 = (const float*)d_in[10];
    const float* W4 = (const float*)d_in[11]; const float* b4 = (const float*)d_in[12];
    const float* W5 = (const float*)d_in[13]; const float* b5 = (const float*)d_in[14];
    const float* W6 = (const float*)d_in[15]; const float* b6 = (const float*)d_in[16];
    float* out = (float*)d_out;

    const int prep_total = G3 * HP + FIN * G3P + G3P
                         + 5 * 256 * 256 + 5 * 256 + 256 * 32 + 32;

    dummy_kernel<<<1, 32>>>();                                      // launch 1
    prep_kernel<<<(prep_total + 511) / 512, 512>>>(                 // launch 2
        W_hh, W_ih, b_ih, W1, b1, W2, b2, W3, b3, W4, b4, W5, b5, W6, b6);
    gi_kernel<<<NSEQ / 2, G3P>>>(history);                          // launch 3
    gru_kernel<<<1, 416>>>(b_hh);                                   // launch 4 (profiled)
    mlp_kernel<<<NSEQ / 2, 256>>>(out);                             // launch 5
}